// round 6
// baseline (speedup 1.0000x reference)
#include <cuda_runtime.h>
#include <cuda_bf16.h>
#include <cstdint>

#define N_Q    4096
#define N_R    65536
#define DIM    512
#define K_TOP  16

#define BM     128
#define BN     128
#define BKB    64               // k-bytes per stage (64 int8)
#define NSPLIT 64
#define CHUNK  (N_R / NSPLIT)   // 1024
#define NT     (CHUNK / BN)     // 8
#define NKT    (DIM / BKB)      // 8
#define TOT    (NT * NKT)       // 64

#define PITCH   80              // bytes per smem row (64 data + 16 pad)
#define STG     (BM * PITCH)    // 10240
#define SC_OFF  (4 * STG)       // 40960
#define SPITCH  130
#define SBC_OFF (SC_OFF + BM * SPITCH * 4)      // 107520
#define SMEM_TOTAL (SBC_OFF + CHUNK * 4)        // 111616

// ---------------- scratch ----------------
__device__ int8_t g_xa[(size_t)N_Q * DIM];               // 2 MB
__device__ float  g_sa[N_Q];
__device__ int8_t g_rq[(size_t)N_R * DIM];               // 32 MB
__device__ float  g_sb[N_R];
__device__ float  g_cand[(size_t)N_Q * NSPLIT * K_TOP];  // 16 MB

// ---------------- helpers ----------------
__device__ __forceinline__ uint32_t smem_u32(const void* p) {
    uint32_t a;
    asm("{ .reg .u64 t; cvta.to.shared.u64 t, %1; cvt.u32.u64 %0, t; }" : "=r"(a) : "l"(p));
    return a;
}
__device__ __forceinline__ void cp_async16(uint32_t dst, const void* src) {
    asm volatile("cp.async.cg.shared.global [%0], [%1], 16;\n" :: "r"(dst), "l"(src));
}
__device__ __forceinline__ void cp_commit() { asm volatile("cp.async.commit_group;\n" ::: "memory"); }
__device__ __forceinline__ void cp_wait_all() { asm volatile("cp.async.wait_group 0;\n" ::: "memory"); }

__device__ __forceinline__ void imma_s8(int* c, const uint32_t* a, const uint32_t* b) {
    asm volatile(
        "mma.sync.aligned.m16n8k32.row.col.s32.s8.s8.s32 "
        "{%0,%1,%2,%3}, {%4,%5,%6,%7}, {%8,%9}, {%0,%1,%2,%3};\n"
        : "+r"(c[0]), "+r"(c[1]), "+r"(c[2]), "+r"(c[3])
        : "r"(a[0]), "r"(a[1]), "r"(a[2]), "r"(a[3]),
          "r"(b[0]), "r"(b[1]));
}
#define LDSM4(r0, r1, r2, r3, addr) \
    asm volatile("ldmatrix.sync.aligned.m8n8.x4.shared.b16 {%0,%1,%2,%3}, [%4];" \
                 : "=r"(r0), "=r"(r1), "=r"(r2), "=r"(r3) : "r"(addr))

// ---------------- prep: normalize x -> int8 + scale ----------------
__global__ void prep_x_kernel(const float* __restrict__ x) {
    int row = blockIdx.x;
    int t = threadIdx.x;  // 128 threads, 4 contiguous elems each
    const float4* xr = (const float4*)(x + (size_t)row * DIM);
    float4 v = xr[t];
    float ss = v.x * v.x + v.y * v.y + v.z * v.z + v.w * v.w;
#pragma unroll
    for (int o = 16; o > 0; o >>= 1) ss += __shfl_xor_sync(0xffffffffu, ss, o);
    __shared__ float red[4];
    if ((t & 31) == 0) red[t >> 5] = ss;
    __syncthreads();
    float inv = 1.0f / fmaxf(sqrtf(red[0] + red[1] + red[2] + red[3]), 1e-12f);
    v.x *= inv; v.y *= inv; v.z *= inv; v.w *= inv;

    float am = fmaxf(fmaxf(fabsf(v.x), fabsf(v.y)), fmaxf(fabsf(v.z), fabsf(v.w)));
#pragma unroll
    for (int o = 16; o > 0; o >>= 1) am = fmaxf(am, __shfl_xor_sync(0xffffffffu, am, o));
    __shared__ float redm[4];
    if ((t & 31) == 0) redm[t >> 5] = am;
    __syncthreads();
    float amax = fmaxf(fmaxf(redm[0], redm[1]), fmaxf(redm[2], redm[3]));
    amax = fmaxf(amax, 1e-12f);
    float qs = amax / 127.0f;
    float rq = 127.0f / amax;

    int a0 = __float2int_rn(v.x * rq), a1 = __float2int_rn(v.y * rq);
    int a2 = __float2int_rn(v.z * rq), a3 = __float2int_rn(v.w * rq);
    uint32_t pk = (uint32_t)(a0 & 0xff) | ((uint32_t)(a1 & 0xff) << 8) |
                  ((uint32_t)(a2 & 0xff) << 16) | ((uint32_t)(a3 & 0xff) << 24);
    ((uint32_t*)(g_xa + (size_t)row * DIM))[t] = pk;
    if (t == 0) g_sa[row] = qs;
}

// ---------------- prep: refs (unit-norm fp32) -> int8 + scale ----------------
__global__ void prep_refs_kernel(const float* __restrict__ r) {
    int row = blockIdx.x * 8 + (threadIdx.x >> 5);   // one warp per row
    int lane = threadIdx.x & 31;
    const float4* rr = (const float4*)(r + (size_t)row * DIM);
    float4 v[4];
    float am = 0.f;
#pragma unroll
    for (int i = 0; i < 4; ++i) {
        v[i] = rr[lane * 4 + i];
        am = fmaxf(am, fmaxf(fmaxf(fabsf(v[i].x), fabsf(v[i].y)),
                             fmaxf(fabsf(v[i].z), fabsf(v[i].w))));
    }
#pragma unroll
    for (int o = 16; o > 0; o >>= 1) am = fmaxf(am, __shfl_xor_sync(0xffffffffu, am, o));
    am = fmaxf(am, 1e-12f);
    float rq = 127.0f / am;
    uint32_t pk[4];
#pragma unroll
    for (int i = 0; i < 4; ++i) {
        int a0 = __float2int_rn(v[i].x * rq), a1 = __float2int_rn(v[i].y * rq);
        int a2 = __float2int_rn(v[i].z * rq), a3 = __float2int_rn(v[i].w * rq);
        pk[i] = (uint32_t)(a0 & 0xff) | ((uint32_t)(a1 & 0xff) << 8) |
                ((uint32_t)(a2 & 0xff) << 16) | ((uint32_t)(a3 & 0xff) << 24);
    }
    ((uint4*)(g_rq + (size_t)row * DIM))[lane] = make_uint4(pk[0], pk[1], pk[2], pk[3]);
    if (lane == 0) g_sb[row] = am / 127.0f;
}

// ---------------- stage loader: A[128][64B] + B[128][64B] ----------------
__device__ __forceinline__ void issue_stage(uint32_t sb_, int buf, int j,
                                            const int8_t* Ag, const int8_t* Bg,
                                            int tid) {
    int nt = j >> 3;
    int kof = (j & 7) * BKB;
    uint32_t abase = sb_ + buf * STG;
    uint32_t bbase = sb_ + 2 * STG + buf * STG;
    const int8_t* Bt = Bg + (size_t)nt * BN * DIM;
#pragma unroll
    for (int h = 0; h < 2; ++h) {
        int ch = tid + h * 256;     // 0..511
        int row = ch >> 2;
        int c = ch & 3;
        cp_async16(abase + row * PITCH + c * 16,
                   Ag + (size_t)row * DIM + kof + c * 16);
        cp_async16(bbase + row * PITCH + c * 16,
                   Bt + (size_t)row * DIM + kof + c * 16);
    }
}

// ---------------- fused int8 GEMM (ldmatrix + imma) + top-16 ----------------
__global__ __launch_bounds__(256, 2) void fused_gemm_topk_kernel() {
    extern __shared__ uint8_t smem[];
    uint32_t sb_ = smem_u32(smem);
    float* sc = (float*)(smem + SC_OFF);
    float* sbc = (float*)(smem + SBC_OFF);

    int tid = threadIdx.x;
    int lane = tid & 31, warp = tid >> 5;
    int m0 = blockIdx.x * BM;
    int n0 = blockIdx.y * CHUNK;
    const int8_t* Ag = g_xa + (size_t)m0 * DIM;
    const int8_t* Bg = g_rq + (size_t)n0 * DIM;

    // preload chunk's sb scales (1024 floats)
#pragma unroll
    for (int h = 0; h < CHUNK / 256; ++h)
        sbc[tid + h * 256] = g_sb[n0 + tid + h * 256];

    int wm = (warp >> 2) * 64;
    int wn = (warp & 3) * 32;
    int g = lane >> 2, q = lane & 3;

    uint32_t aoff = (uint32_t)((lane & 15) * PITCH + (lane >> 4) * 16);
    uint32_t boff = (uint32_t)((((lane >> 4) * 8) + (lane & 7)) * PITCH +
                               ((lane >> 3) & 1) * 16);

    int myrow = tid >> 1;          // query row owned for scan
    int half = tid & 1;

    float t16[K_TOP];
#pragma unroll
    for (int j = 0; j < K_TOP; ++j) t16[j] = -1e30f;

    int acc[16][4];
#pragma unroll
    for (int i = 0; i < 16; ++i)
#pragma unroll
        for (int j = 0; j < 4; ++j) acc[i][j] = 0;

    issue_stage(sb_, 0, 0, Ag, Bg, tid);
    cp_commit();

    int it = 0;
    for (int nt = 0; nt < NT; ++nt) {
        for (int kt = 0; kt < NKT; ++kt) {
            cp_wait_all();
            __syncthreads();
            if (it + 1 < TOT) {
                issue_stage(sb_, (it + 1) & 1, it + 1, Ag, Bg, tid);
                cp_commit();
            }
            int buf = it & 1;
            uint32_t abase = sb_ + buf * STG;
            uint32_t bbase = sb_ + 2 * STG + buf * STG;
#pragma unroll
            for (int kk = 0; kk < 2; ++kk) {
                uint32_t af[4][4], bf2[4][2];
#pragma unroll
                for (int mf = 0; mf < 4; ++mf) {
                    uint32_t ad = abase + (wm + mf * 16) * PITCH + kk * 32 + aoff;
                    LDSM4(af[mf][0], af[mf][1], af[mf][2], af[mf][3], ad);
                }
#pragma unroll
                for (int pr = 0; pr < 2; ++pr) {
                    uint32_t bd = bbase + (wn + pr * 16) * PITCH + kk * 32 + boff;
                    LDSM4(bf2[pr * 2][0], bf2[pr * 2][1],
                          bf2[pr * 2 + 1][0], bf2[pr * 2 + 1][1], bd);
                }
#pragma unroll
                for (int mf = 0; mf < 4; ++mf)
#pragma unroll
                    for (int nf = 0; nf < 4; ++nf)
                        imma_s8(acc[mf * 4 + nf], af[mf], bf2[nf]);
            }
            ++it;
        }

        // spill tile (int -> exact float) to smem
        __syncthreads();
#pragma unroll
        for (int mf = 0; mf < 4; ++mf) {
#pragma unroll
            for (int nf = 0; nf < 4; ++nf) {
                int r0 = wm + mf * 16 + g;
                int c0 = wn + nf * 8 + q * 2;
                sc[r0 * SPITCH + c0]           = (float)acc[mf * 4 + nf][0];
                sc[r0 * SPITCH + c0 + 1]       = (float)acc[mf * 4 + nf][1];
                sc[(r0 + 8) * SPITCH + c0]     = (float)acc[mf * 4 + nf][2];
                sc[(r0 + 8) * SPITCH + c0 + 1] = (float)acc[mf * 4 + nf][3];
                acc[mf * 4 + nf][0] = 0; acc[mf * 4 + nf][1] = 0;
                acc[mf * 4 + nf][2] = 0; acc[mf * 4 + nf][3] = 0;
            }
        }
        __syncthreads();

        // scan with per-col sb scale (sa is row-uniform -> rank-invariant)
        {
            const float* rowp = sc + myrow * SPITCH + half * 64;
            const float* sbp = sbc + nt * BN + half * 64;
            float th = t16[K_TOP - 1];
#pragma unroll 8
            for (int j = 0; j < 64; ++j) {
                float v = rowp[j] * sbp[j];
                if (v > th) {
                    t16[K_TOP - 1] = v;
#pragma unroll
                    for (int p = K_TOP - 1; p > 0; --p) {
                        float a = t16[p - 1], bb = t16[p];
                        t16[p - 1] = fmaxf(a, bb);
                        t16[p]     = fminf(a, bb);
                    }
                    th = t16[K_TOP - 1];
                }
            }
        }
        __syncthreads();
    }

    // pair-merge col-halves, apply sa, write candidates
    float* lists = sc;
#pragma unroll
    for (int j = 0; j < K_TOP; ++j) lists[tid * K_TOP + j] = t16[j];
    __syncthreads();

    if (half == 0) {
        const float* a = &lists[tid * K_TOP];
        const float* b = &lists[(tid + 1) * K_TOP];
        float sa = g_sa[m0 + myrow];
        float m[K_TOP];
        int ia = 0, ib = 0;
#pragma unroll
        for (int j = 0; j < K_TOP; ++j) {
            float av = a[ia], bv = b[ib];
            if (av >= bv) { m[j] = av; ++ia; }
            else          { m[j] = bv; ++ib; }
        }
        float* outp = g_cand + ((size_t)(m0 + myrow) * NSPLIT + blockIdx.y) * K_TOP;
#pragma unroll
        for (int j = 0; j < K_TOP; ++j) outp[j] = m[j] * sa;
    }
}

// ---------------- final merge + weights ----------------
__global__ __launch_bounds__(NSPLIT) void merge_kernel(float* __restrict__ out) {
    int qy = blockIdx.x;
    int s = threadIdx.x;   // 0..63
    __shared__ float sm[NSPLIT * K_TOP];
    const float* cp = g_cand + ((size_t)qy * NSPLIT + s) * K_TOP;
#pragma unroll
    for (int j = 0; j < K_TOP; ++j) sm[s * K_TOP + j] = cp[j];
    __syncthreads();

    for (int halfs = NSPLIT / 2; halfs >= 1; halfs >>= 1) {
        if (s < halfs) {
            float* a = &sm[s * K_TOP];
            float* b = &sm[(s + halfs) * K_TOP];
            float m[K_TOP];
            int ia = 0, ib = 0;
#pragma unroll
            for (int j = 0; j < K_TOP; ++j) {
                float av = a[ia], bv = b[ib];
                if (av >= bv) { m[j] = av; ++ia; }
                else          { m[j] = bv; ++ib; }
            }
#pragma unroll
            for (int j = 0; j < K_TOP; ++j) a[j] = m[j];
        }
        __syncthreads();
    }

    if (s == 0) {
        float w[K_TOP];
        float ssum = 0.f;
#pragma unroll
        for (int j = 0; j < K_TOP; ++j) {
            float d2 = fmaxf(2.0f - 2.0f * sm[j], 1e-12f);
            w[j] = expf(-sqrtf(d2));
            ssum += w[j];
        }
        float inv = 1.0f / fmaxf(ssum, 1e-12f);
#pragma unroll
        for (int j = 0; j < K_TOP; ++j)
            out[(size_t)qy * K_TOP + j] = w[j] * inv;
    }
}

// ---------------- launch ----------------
extern "C" void kernel_launch(void* const* d_in, const int* in_sizes, int n_in,
                              void* d_out, int out_size) {
    const float* x    = (const float*)d_in[0];
    const float* refs = (const float*)d_in[1];
    float* out = (float*)d_out;

    static bool attr_set = false;
    if (!attr_set) {
        cudaFuncSetAttribute(fused_gemm_topk_kernel,
                             cudaFuncAttributeMaxDynamicSharedMemorySize, SMEM_TOTAL);
        attr_set = true;
    }

    prep_x_kernel<<<N_Q, 128>>>(x);
    prep_refs_kernel<<<N_R / 8, 256>>>(refs);
    fused_gemm_topk_kernel<<<dim3(N_Q / BM, NSPLIT), 256, SMEM_TOTAL>>>();
    merge_kernel<<<N_Q, NSPLIT>>>(out);
}

// round 7
// speedup vs baseline: 1.7030x; 1.7030x over previous
#include <cuda_runtime.h>
#include <cuda_fp16.h>
#include <cstdint>

#define N_Q    4096
#define N_R    65536
#define DIM    512
#define K_TOP  16

#define BM     128
#define BN     128
#define BK     32
#define NSPLIT 64
#define CHUNK  (N_R / NSPLIT)   // 1024
#define NT     (CHUNK / BN)     // 8
#define NKT    (DIM / BK)       // 16
#define TOT    (NT * NKT)       // 128

#define PITCH   80              // bytes per smem row (64 data + 16 pad)
#define STG     (BM * PITCH)    // 10240
#define SC_OFF  (4 * STG)       // 40960
#define SPITCH  130
#define SMEM_TOTAL (SC_OFF + BM * SPITCH * 4)   // 107520

// ---------------- scratch ----------------
__device__ __half g_xh[(size_t)N_Q * DIM];               // 4 MB
__device__ __half g_rh[(size_t)N_R * DIM];               // 64 MB
__device__ float  g_cand[(size_t)N_Q * NSPLIT * K_TOP];  // 16 MB

// ---------------- helpers ----------------
__device__ __forceinline__ uint32_t smem_u32(const void* p) {
    uint32_t a;
    asm("{ .reg .u64 t; cvta.to.shared.u64 t, %1; cvt.u32.u64 %0, t; }" : "=r"(a) : "l"(p));
    return a;
}
__device__ __forceinline__ void cp_async16(uint32_t dst, const void* src) {
    asm volatile("cp.async.cg.shared.global [%0], [%1], 16;\n" :: "r"(dst), "l"(src));
}
__device__ __forceinline__ void cp_commit() { asm volatile("cp.async.commit_group;\n" ::: "memory"); }
__device__ __forceinline__ void cp_wait_all() { asm volatile("cp.async.wait_group 0;\n" ::: "memory"); }

// f16 inputs, f16 accumulators (2 packed regs)
__device__ __forceinline__ void mma_f16acc(uint32_t* c, const uint32_t* a, const uint32_t* b) {
    asm volatile(
        "mma.sync.aligned.m16n8k16.row.col.f16.f16.f16.f16 "
        "{%0,%1}, {%2,%3,%4,%5}, {%6,%7}, {%0,%1};\n"
        : "+r"(c[0]), "+r"(c[1])
        : "r"(a[0]), "r"(a[1]), "r"(a[2]), "r"(a[3]),
          "r"(b[0]), "r"(b[1]));
}
#define LDSM4(r0, r1, r2, r3, addr) \
    asm volatile("ldmatrix.sync.aligned.m8n8.x4.shared.b16 {%0,%1,%2,%3}, [%4];" \
                 : "=r"(r0), "=r"(r1), "=r"(r2), "=r"(r3) : "r"(addr))

// ---------------- prep: normalize x -> f16 ----------------
__global__ void prep_x_kernel(const float* __restrict__ x) {
    int row = blockIdx.x;
    int t = threadIdx.x;
    const float* xr = x + (size_t)row * DIM;
    float v[4];
    float ss = 0.f;
#pragma unroll
    for (int i = 0; i < 4; ++i) { v[i] = xr[i * 128 + t]; ss += v[i] * v[i]; }
#pragma unroll
    for (int o = 16; o > 0; o >>= 1) ss += __shfl_xor_sync(0xffffffffu, ss, o);
    __shared__ float red[4];
    if ((t & 31) == 0) red[t >> 5] = ss;
    __syncthreads();
    float tot = red[0] + red[1] + red[2] + red[3];
    float scale = 1.0f / fmaxf(sqrtf(tot), 1e-12f);
#pragma unroll
    for (int i = 0; i < 4; ++i)
        g_xh[(size_t)row * DIM + i * 128 + t] = __float2half(v[i] * scale);
}

// ---------------- prep: refs fp32 -> f16 ----------------
__global__ void conv_refs_kernel(const float* __restrict__ r) {
    size_t total4 = (size_t)N_R * DIM / 4;
    const float4* r4 = (const float4*)r;
    __half2* out2 = (__half2*)g_rh;
    for (size_t i = (size_t)blockIdx.x * blockDim.x + threadIdx.x; i < total4;
         i += (size_t)gridDim.x * blockDim.x) {
        float4 f = r4[i];
        out2[i * 2]     = __floats2half2_rn(f.x, f.y);
        out2[i * 2 + 1] = __floats2half2_rn(f.z, f.w);
    }
}

// ---------------- stage loader: A[128][32] + B[128][32] f16 ----------------
__device__ __forceinline__ void issue_stage(uint32_t sb, int buf, int j,
                                            const __half* Ag, const __half* Bg,
                                            int tid) {
    int nt = j >> 4;
    int kof = (j & 15) * BK;
    uint32_t abase = sb + buf * STG;
    uint32_t bbase = sb + 2 * STG + buf * STG;
    const __half* Bt = Bg + (size_t)nt * BN * DIM;
#pragma unroll
    for (int h = 0; h < 2; ++h) {
        int ch = tid + h * 256;     // 0..511
        int row = ch >> 2;
        int c = ch & 3;
        cp_async16(abase + row * PITCH + c * 16,
                   Ag + (size_t)row * DIM + kof + c * 8);
        cp_async16(bbase + row * PITCH + c * 16,
                   Bt + (size_t)row * DIM + kof + c * 8);
    }
}

// ---------------- fused GEMM (f16 accum) + top-16 ----------------
__global__ __launch_bounds__(256, 2) void fused_gemm_topk_kernel() {
    extern __shared__ uint8_t smem[];
    uint32_t sb = smem_u32(smem);
    float* sc = (float*)(smem + SC_OFF);

    int tid = threadIdx.x;
    int lane = tid & 31, warp = tid >> 5;
    int m0 = blockIdx.x * BM;
    int n0 = blockIdx.y * CHUNK;
    const __half* Ag = g_xh + (size_t)m0 * DIM;
    const __half* Bg = g_rh + (size_t)n0 * DIM;

    int wm = (warp >> 2) * 64;
    int wn = (warp & 3) * 32;
    int g = lane >> 2, q = lane & 3;

    uint32_t aoff = (uint32_t)((lane & 15) * PITCH + (lane >> 4) * 16);
    uint32_t boff = (uint32_t)((((lane >> 4) * 8) + (lane & 7)) * PITCH +
                               ((lane >> 3) & 1) * 16);

    int myrow = tid >> 1;
    int half_ = tid & 1;

    float t16[K_TOP];
#pragma unroll
    for (int j = 0; j < K_TOP; ++j) t16[j] = -1e30f;

    uint32_t acc[16][2];
#pragma unroll
    for (int i = 0; i < 16; ++i) { acc[i][0] = 0u; acc[i][1] = 0u; }

    issue_stage(sb, 0, 0, Ag, Bg, tid);
    cp_commit();

    int it = 0;
    for (int nt = 0; nt < NT; ++nt) {
        for (int kt = 0; kt < NKT; ++kt) {
            cp_wait_all();
            __syncthreads();
            if (it + 1 < TOT) {
                issue_stage(sb, (it + 1) & 1, it + 1, Ag, Bg, tid);
                cp_commit();
            }
            int buf = it & 1;
            uint32_t abase = sb + buf * STG;
            uint32_t bbase = sb + 2 * STG + buf * STG;
#pragma unroll
            for (int kk = 0; kk < 2; ++kk) {
                uint32_t af[4][4], bf2[4][2];
#pragma unroll
                for (int mf = 0; mf < 4; ++mf) {
                    uint32_t ad = abase + (wm + mf * 16) * PITCH + kk * 32 + aoff;
                    LDSM4(af[mf][0], af[mf][1], af[mf][2], af[mf][3], ad);
                }
#pragma unroll
                for (int pr = 0; pr < 2; ++pr) {
                    uint32_t bd = bbase + (wn + pr * 16) * PITCH + kk * 32 + boff;
                    LDSM4(bf2[pr * 2][0], bf2[pr * 2][1],
                          bf2[pr * 2 + 1][0], bf2[pr * 2 + 1][1], bd);
                }
#pragma unroll
                for (int mf = 0; mf < 4; ++mf)
#pragma unroll
                    for (int nf = 0; nf < 4; ++nf)
                        mma_f16acc(acc[mf * 4 + nf], af[mf], bf2[nf]);
            }
            ++it;
        }

        // spill tile scores (f16 accum -> f32) to smem
        __syncthreads();
#pragma unroll
        for (int mf = 0; mf < 4; ++mf) {
#pragma unroll
            for (int nf = 0; nf < 4; ++nf) {
                int r0 = wm + mf * 16 + g;
                int c0 = wn + nf * 8 + q * 2;
                float2 lo = __half22float2(*(__half2*)&acc[mf * 4 + nf][0]);
                float2 hi = __half22float2(*(__half2*)&acc[mf * 4 + nf][1]);
                sc[r0 * SPITCH + c0]           = lo.x;
                sc[r0 * SPITCH + c0 + 1]       = lo.y;
                sc[(r0 + 8) * SPITCH + c0]     = hi.x;
                sc[(r0 + 8) * SPITCH + c0 + 1] = hi.y;
                acc[mf * 4 + nf][0] = 0u;
                acc[mf * 4 + nf][1] = 0u;
            }
        }
        __syncthreads();

        // top-k scan: thread owns (row tid>>1, cols (tid&1)*64 .. +63)
        {
            const float* rowp = sc + myrow * SPITCH + half_ * 64;
            float th = t16[K_TOP - 1];
#pragma unroll 8
            for (int j = 0; j < 64; ++j) {
                float v = rowp[j];
                if (v > th) {
                    t16[K_TOP - 1] = v;
#pragma unroll
                    for (int p = K_TOP - 1; p > 0; --p) {
                        float a = t16[p - 1], bb = t16[p];
                        t16[p - 1] = fmaxf(a, bb);
                        t16[p]     = fminf(a, bb);
                    }
                    th = t16[K_TOP - 1];
                }
            }
        }
        __syncthreads();
    }

    // pair-merge col-halves, write candidates
    float* lists = sc;
#pragma unroll
    for (int j = 0; j < K_TOP; ++j) lists[tid * K_TOP + j] = t16[j];
    __syncthreads();

    if (half_ == 0) {
        const float* a = &lists[tid * K_TOP];
        const float* b = &lists[(tid + 1) * K_TOP];
        float m[K_TOP];
        int ia = 0, ib = 0;
#pragma unroll
        for (int j = 0; j < K_TOP; ++j) {
            float av = a[ia], bv = b[ib];
            if (av >= bv) { m[j] = av; ++ia; }
            else          { m[j] = bv; ++ib; }
        }
        float* outp = g_cand + ((size_t)(m0 + myrow) * NSPLIT + blockIdx.y) * K_TOP;
#pragma unroll
        for (int j = 0; j < K_TOP; ++j) outp[j] = m[j];
    }
}

// ---------------- final merge + weights ----------------
__global__ __launch_bounds__(NSPLIT) void merge_kernel(float* __restrict__ out) {
    int qy = blockIdx.x;
    int s = threadIdx.x;   // 0..63
    __shared__ float sm[NSPLIT * K_TOP];
    const float* cp = g_cand + ((size_t)qy * NSPLIT + s) * K_TOP;
#pragma unroll
    for (int j = 0; j < K_TOP; ++j) sm[s * K_TOP + j] = cp[j];
    __syncthreads();

    for (int half = NSPLIT / 2; half >= 1; half >>= 1) {
        if (s < half) {
            float* a = &sm[s * K_TOP];
            float* b = &sm[(s + half) * K_TOP];
            float m[K_TOP];
            int ia = 0, ib = 0;
#pragma unroll
            for (int j = 0; j < K_TOP; ++j) {
                float av = a[ia], bv = b[ib];
                if (av >= bv) { m[j] = av; ++ia; }
                else          { m[j] = bv; ++ib; }
            }
#pragma unroll
            for (int j = 0; j < K_TOP; ++j) a[j] = m[j];
        }
        __syncthreads();
    }

    if (s == 0) {
        float w[K_TOP];
        float ssum = 0.f;
#pragma unroll
        for (int j = 0; j < K_TOP; ++j) {
            float d2 = fmaxf(2.0f - 2.0f * sm[j], 1e-12f);
            w[j] = expf(-sqrtf(d2));
            ssum += w[j];
        }
        float inv = 1.0f / fmaxf(ssum, 1e-12f);
#pragma unroll
        for (int j = 0; j < K_TOP; ++j)
            out[(size_t)qy * K_TOP + j] = w[j] * inv;
    }
}

// ---------------- launch ----------------
extern "C" void kernel_launch(void* const* d_in, const int* in_sizes, int n_in,
                              void* d_out, int out_size) {
    const float* x    = (const float*)d_in[0];
    const float* refs = (const float*)d_in[1];
    float* out = (float*)d_out;

    static bool attr_set = false;
    if (!attr_set) {
        cudaFuncSetAttribute(fused_gemm_topk_kernel,
                             cudaFuncAttributeMaxDynamicSharedMemorySize, SMEM_TOTAL);
        attr_set = true;
    }

    prep_x_kernel<<<N_Q, 128>>>(x);
    conv_refs_kernel<<<16384, 256>>>(refs);
    fused_gemm_topk_kernel<<<dim3(N_Q / BM, NSPLIT), 256, SMEM_TOTAL>>>();
    merge_kernel<<<N_Q, NSPLIT>>>(out);
}

// round 8
// speedup vs baseline: 1.9824x; 1.1641x over previous
#include <cuda_runtime.h>
#include <cuda_fp16.h>
#include <cstdint>

#define N_Q    4096
#define N_R    65536
#define DIM    512
#define K_TOP  16

#define BM     128
#define BN     256
#define BK     32
#define NSPLIT 64
#define CHUNK  (N_R / NSPLIT)   // 1024
#define NT     (CHUNK / BN)     // 4
#define NKT    (DIM / BK)       // 16
#define TOT    (NT * NKT)       // 64

#define PITCH   80                  // bytes per smem row (64 data + 16 pad)
#define A_STG   (BM * PITCH)        // 10240
#define B_STG   (BN * PITCH)        // 20480
#define A_OFF   0
#define B_OFF   (2 * A_STG)         // 20480
#define SP_OFF  (B_OFF + 2 * B_STG) // 61440  (spill: 128 rows x 68 uint32)
#define SPITCH_U 68                 // uint32 per spill row (64 data + 4 pad)
#define TS_OFF  (SP_OFF + BM * SPITCH_U * 4)   // 96256 (ts: 256 x 17 floats)
#define SMEM_TOTAL (TS_OFF + 256 * 17 * 4)     // 113664

// ---------------- scratch ----------------
__device__ __half g_xh[(size_t)N_Q * DIM];               // 4 MB
__device__ __half g_rh[(size_t)N_R * DIM];               // 64 MB
__device__ float  g_cand[(size_t)N_Q * NSPLIT * K_TOP];  // 16 MB

// ---------------- helpers ----------------
__device__ __forceinline__ uint32_t smem_u32(const void* p) {
    uint32_t a;
    asm("{ .reg .u64 t; cvta.to.shared.u64 t, %1; cvt.u32.u64 %0, t; }" : "=r"(a) : "l"(p));
    return a;
}
__device__ __forceinline__ void cp_async16(uint32_t dst, const void* src) {
    asm volatile("cp.async.cg.shared.global [%0], [%1], 16;\n" :: "r"(dst), "l"(src));
}
__device__ __forceinline__ void cp_commit() { asm volatile("cp.async.commit_group;\n" ::: "memory"); }
__device__ __forceinline__ void cp_wait_all() { asm volatile("cp.async.wait_group 0;\n" ::: "memory"); }

__device__ __forceinline__ void mma_f16acc(uint32_t* c, const uint32_t* a, const uint32_t* b) {
    asm volatile(
        "mma.sync.aligned.m16n8k16.row.col.f16.f16.f16.f16 "
        "{%0,%1}, {%2,%3,%4,%5}, {%6,%7}, {%0,%1};\n"
        : "+r"(c[0]), "+r"(c[1])
        : "r"(a[0]), "r"(a[1]), "r"(a[2]), "r"(a[3]),
          "r"(b[0]), "r"(b[1]));
}
#define LDSM4(r0, r1, r2, r3, addr) \
    asm volatile("ldmatrix.sync.aligned.m8n8.x4.shared.b16 {%0,%1,%2,%3}, [%4];" \
                 : "=r"(r0), "=r"(r1), "=r"(r2), "=r"(r3) : "r"(addr))

// ---------------- prep: normalize x -> f16 ----------------
__global__ void prep_x_kernel(const float* __restrict__ x) {
    int row = blockIdx.x;
    int t = threadIdx.x;
    const float* xr = x + (size_t)row * DIM;
    float v[4];
    float ss = 0.f;
#pragma unroll
    for (int i = 0; i < 4; ++i) { v[i] = xr[i * 128 + t]; ss += v[i] * v[i]; }
#pragma unroll
    for (int o = 16; o > 0; o >>= 1) ss += __shfl_xor_sync(0xffffffffu, ss, o);
    __shared__ float red[4];
    if ((t & 31) == 0) red[t >> 5] = ss;
    __syncthreads();
    float tot = red[0] + red[1] + red[2] + red[3];
    float scale = 1.0f / fmaxf(sqrtf(tot), 1e-12f);
#pragma unroll
    for (int i = 0; i < 4; ++i)
        g_xh[(size_t)row * DIM + i * 128 + t] = __float2half(v[i] * scale);
}

// ---------------- prep: refs fp32 -> f16 ----------------
__global__ void conv_refs_kernel(const float* __restrict__ r) {
    size_t total4 = (size_t)N_R * DIM / 4;
    const float4* r4 = (const float4*)r;
    __half2* out2 = (__half2*)g_rh;
    for (size_t i = (size_t)blockIdx.x * blockDim.x + threadIdx.x; i < total4;
         i += (size_t)gridDim.x * blockDim.x) {
        float4 f = r4[i];
        out2[i * 2]     = __floats2half2_rn(f.x, f.y);
        out2[i * 2 + 1] = __floats2half2_rn(f.z, f.w);
    }
}

// ---------------- stage loader: A[128][32] + B[256][32] f16 ----------------
__device__ __forceinline__ void issue_stage(uint32_t sb, int buf, int j,
                                            const __half* Ag, const __half* Bg,
                                            int tid) {
    int nt = j >> 4;
    int kof = (j & 15) * BK;
    uint32_t abase = sb + A_OFF + buf * A_STG;
    uint32_t bbase = sb + B_OFF + buf * B_STG;
    const __half* Bt = Bg + (size_t)nt * BN * DIM;
    // A: 512 x 16B chunks
#pragma unroll
    for (int h = 0; h < 2; ++h) {
        int ch = tid + h * 256;
        int row = ch >> 2, c = ch & 3;
        cp_async16(abase + row * PITCH + c * 16,
                   Ag + (size_t)row * DIM + kof + c * 8);
    }
    // B: 1024 x 16B chunks
#pragma unroll
    for (int h = 0; h < 4; ++h) {
        int ch = tid + h * 256;
        int row = ch >> 2, c = ch & 3;
        cp_async16(bbase + row * PITCH + c * 16,
                   Bt + (size_t)row * DIM + kof + c * 8);
    }
}

// ---------------- fused GEMM (64x64 warp tiles, f16 acc) + top-16 ----------------
__global__ __launch_bounds__(256, 2) void fused_gemm_topk_kernel() {
    extern __shared__ uint8_t smem[];
    uint32_t sb = smem_u32(smem);
    uint32_t* sp = (uint32_t*)(smem + SP_OFF);   // spill: [128][68] uint32 (half2)
    float*    ts = (float*)(smem + TS_OFF);      // [256][17] per-thread top-16

    int tid = threadIdx.x;
    int lane = tid & 31, warp = tid >> 5;
    int m0 = blockIdx.x * BM;
    int n0 = blockIdx.y * CHUNK;
    const __half* Ag = g_xh + (size_t)m0 * DIM;
    const __half* Bg = g_rh + (size_t)n0 * DIM;

    int wm = (warp >> 2) * 64;        // 0 / 64
    int wn = (warp & 3) * 64;         // 0 / 64 / 128 / 192
    int wph = (warp & 3) >> 1;        // spill phase this warp writes (0: cols<128)
    int wnl = (wn & 127);             // col offset within phase
    int g = lane >> 2, q = lane & 3;

    uint32_t aoff = (uint32_t)((lane & 15) * PITCH + (lane >> 4) * 16);
    uint32_t boff = (uint32_t)((((lane >> 4) * 8) + (lane & 7)) * PITCH +
                               ((lane >> 3) & 1) * 16);

    int myrow = tid >> 1;
    int half_ = tid & 1;

    // init per-thread top-16 in smem
#pragma unroll
    for (int j = 0; j < K_TOP; ++j) ts[tid * 17 + j] = -1e30f;

    uint32_t acc[32][2];
#pragma unroll
    for (int i = 0; i < 32; ++i) { acc[i][0] = 0u; acc[i][1] = 0u; }

    issue_stage(sb, 0, 0, Ag, Bg, tid);
    cp_commit();

    int it = 0;
    for (int nt = 0; nt < NT; ++nt) {
        for (int kt = 0; kt < NKT; ++kt) {
            cp_wait_all();
            __syncthreads();
            if (it + 1 < TOT) {
                issue_stage(sb, (it + 1) & 1, it + 1, Ag, Bg, tid);
                cp_commit();
            }
            int buf = it & 1;
            uint32_t abase = sb + A_OFF + buf * A_STG;
            uint32_t bbase = sb + B_OFF + buf * B_STG;
#pragma unroll
            for (int kk = 0; kk < 2; ++kk) {
                uint32_t af[4][4], bf[8][2];
#pragma unroll
                for (int mf = 0; mf < 4; ++mf) {
                    uint32_t ad = abase + (wm + mf * 16) * PITCH + kk * 32 + aoff;
                    LDSM4(af[mf][0], af[mf][1], af[mf][2], af[mf][3], ad);
                }
#pragma unroll
                for (int pr = 0; pr < 4; ++pr) {
                    uint32_t bd = bbase + (wn + pr * 16) * PITCH + kk * 32 + boff;
                    LDSM4(bf[pr * 2][0], bf[pr * 2][1],
                          bf[pr * 2 + 1][0], bf[pr * 2 + 1][1], bd);
                }
#pragma unroll
                for (int mf = 0; mf < 4; ++mf)
#pragma unroll
                    for (int nf = 0; nf < 8; ++nf)
                        mma_f16acc(acc[mf * 8 + nf], af[mf], bf[nf]);
            }
            ++it;
        }

        // epilogue: two 128-col phases
#pragma unroll
        for (int p = 0; p < 2; ++p) {
            __syncthreads();
            if (wph == p) {
#pragma unroll
                for (int mf = 0; mf < 4; ++mf) {
#pragma unroll
                    for (int nf = 0; nf < 8; ++nf) {
                        int r0 = wm + mf * 16 + g;
                        int cu = (wnl + nf * 8 + q * 2) >> 1;   // uint32 (half2) index
                        sp[r0 * SPITCH_U + cu]       = acc[mf * 8 + nf][0];
                        sp[(r0 + 8) * SPITCH_U + cu] = acc[mf * 8 + nf][1];
                    }
                }
            }
            __syncthreads();
            // all threads scan: row=myrow, 32 half2 (=64 cols) each
            {
                float t16[K_TOP];
#pragma unroll
                for (int j = 0; j < K_TOP; ++j) t16[j] = ts[tid * 17 + j];
                const uint32_t* rowp = sp + myrow * SPITCH_U + half_ * 32;
                float th = t16[K_TOP - 1];
#pragma unroll 8
                for (int j = 0; j < 32; ++j) {
                    __half2 h2 = *(const __half2*)&rowp[j];
                    float2 f2 = __half22float2(h2);
#pragma unroll
                    for (int e = 0; e < 2; ++e) {
                        float v = (e == 0) ? f2.x : f2.y;
                        if (v > th) {
                            t16[K_TOP - 1] = v;
#pragma unroll
                            for (int pp = K_TOP - 1; pp > 0; --pp) {
                                float a = t16[pp - 1], bb = t16[pp];
                                t16[pp - 1] = fmaxf(a, bb);
                                t16[pp]     = fminf(a, bb);
                            }
                            th = t16[K_TOP - 1];
                        }
                    }
                }
#pragma unroll
                for (int j = 0; j < K_TOP; ++j) ts[tid * 17 + j] = t16[j];
            }
        }
        // zero accumulators for next n-tile
#pragma unroll
        for (int i = 0; i < 32; ++i) { acc[i][0] = 0u; acc[i][1] = 0u; }
    }

    // pair-merge the two col-halves of each row, write candidates
    __syncthreads();
    if (half_ == 0) {
        const float* a = &ts[tid * 17];
        const float* b = &ts[(tid + 1) * 17];
        float m[K_TOP];
        int ia = 0, ib = 0;
#pragma unroll
        for (int j = 0; j < K_TOP; ++j) {
            float av = a[ia], bv = b[ib];
            if (av >= bv) { m[j] = av; ++ia; }
            else          { m[j] = bv; ++ib; }
        }
        float* outp = g_cand + ((size_t)(m0 + myrow) * NSPLIT + blockIdx.y) * K_TOP;
#pragma unroll
        for (int j = 0; j < K_TOP; ++j) outp[j] = m[j];
    }
}

// ---------------- final merge + weights (4 queries / block) ----------------
__global__ __launch_bounds__(256) void merge_kernel(float* __restrict__ out) {
    int qy = blockIdx.x * 4 + (threadIdx.x >> 6);
    int s = threadIdx.x & 63;
    __shared__ float sm[4][NSPLIT * K_TOP];
    float* mysm = sm[threadIdx.x >> 6];
    const float* cp = g_cand + ((size_t)qy * NSPLIT + s) * K_TOP;
#pragma unroll
    for (int j = 0; j < K_TOP; ++j) mysm[s * K_TOP + j] = cp[j];
    __syncthreads();

    for (int half = NSPLIT / 2; half >= 1; half >>= 1) {
        if (s < half) {
            float* a = &mysm[s * K_TOP];
            float* b = &mysm[(s + half) * K_TOP];
            float m[K_TOP];
            int ia = 0, ib = 0;
#pragma unroll
            for (int j = 0; j < K_TOP; ++j) {
                float av = a[ia], bv = b[ib];
                if (av >= bv) { m[j] = av; ++ia; }
                else          { m[j] = bv; ++ib; }
            }
#pragma unroll
            for (int j = 0; j < K_TOP; ++j) a[j] = m[j];
        }
        __syncthreads();
    }

    if (s == 0) {
        float w[K_TOP];
        float ssum = 0.f;
#pragma unroll
        for (int j = 0; j < K_TOP; ++j) {
            float d2 = fmaxf(2.0f - 2.0f * mysm[j], 1e-12f);
            w[j] = expf(-sqrtf(d2));
            ssum += w[j];
        }
        float inv = 1.0f / fmaxf(ssum, 1e-12f);
#pragma unroll
        for (int j = 0; j < K_TOP; ++j)
            out[(size_t)qy * K_TOP + j] = w[j] * inv;
    }
}

// ---------------- launch ----------------
extern "C" void kernel_launch(void* const* d_in, const int* in_sizes, int n_in,
                              void* d_out, int out_size) {
    const float* x    = (const float*)d_in[0];
    const float* refs = (const float*)d_in[1];
    float* out = (float*)d_out;

    static bool attr_set = false;
    if (!attr_set) {
        cudaFuncSetAttribute(fused_gemm_topk_kernel,
                             cudaFuncAttributeMaxDynamicSharedMemorySize, SMEM_TOTAL);
        attr_set = true;
    }

    prep_x_kernel<<<N_Q, 128>>>(x);
    conv_refs_kernel<<<16384, 256>>>(refs);
    fused_gemm_topk_kernel<<<dim3(N_Q / BM, NSPLIT), 256, SMEM_TOTAL>>>();
    merge_kernel<<<N_Q / 4, 256>>>(out);
}